// round 1
// baseline (speedup 1.0000x reference)
#include <cuda_runtime.h>

// Problem shape (fixed by the dataset)
#define TT 4096
#define NB 16
#define CC 512
#define NC (NB * CC)            // 8192 columns
#define CHUNK 64
#define NCHUNKS (TT / CHUNK)    // 64
#define TOTAL (TT * NC)         // 33,554,432 floats for new_x

// Static scratch (no allocations allowed)
__device__ float g_partial[NCHUNKS * NC];   // 2 MB: per-chunk column sums -> exclusive prefixes
__device__ float g_rcp[TT * NB];            // 256 KB: 1/(t+1+len_n), layout [t][n]

// k0: reciprocal table. 65536 threads, negligible cost; keeps MUFU out of the hot loop.
__global__ void k0_rcp(const int* __restrict__ cached_len) {
    int idx = blockIdx.x * blockDim.x + threadIdx.x;
    if (idx >= TT * NB) return;
    int n = idx & (NB - 1);
    int t = idx >> 4;
    g_rcp[idx] = 1.0f / ((float)(t + 1) + (float)cached_len[n]);
}

// k1: per-(chunk, n, c) partial sums over 64 timesteps. Coalesced 128B/warp loads.
__global__ void k1_partial(const float* __restrict__ x) {
    int idx = blockIdx.x * blockDim.x + threadIdx.x;   // 0 .. NCHUNKS*NC-1
    int nc = idx & (NC - 1);
    int chunk = idx >> 13;
    const float* p = x + (size_t)chunk * CHUNK * NC + nc;
    float s = 0.0f;
#pragma unroll 8
    for (int i = 0; i < CHUNK; i++) s += p[(size_t)i * NC];
    g_partial[idx] = s;
}

// k1b: per-column exclusive scan of the 64 chunk sums, seeded with cached_avg*len.
// Only 8192 threads; table is L2-resident.
__global__ void k1b_scan(const int* __restrict__ cached_len,
                         const float* __restrict__ cached_avg) {
    int nc = blockIdx.x * blockDim.x + threadIdx.x;
    if (nc >= NC) return;
    int n = nc >> 9;                                    // c fastest, C=512
    float run = cached_avg[nc] * (float)cached_len[n];
#pragma unroll
    for (int ch = 0; ch < NCHUNKS; ch++) {
        float v = g_partial[ch * NC + nc];
        g_partial[ch * NC + nc] = run;
        run += v;
    }
}

// k2: final scan. Each thread rescans its 64-element chunk starting from the
// exclusive prefix, multiplying by the precomputed reciprocal (matches the
// reference, which also multiplies by 1/counts).
__global__ void k2_scan(const float* __restrict__ x,
                        const int* __restrict__ cached_len,
                        float* __restrict__ out, int extras) {
    int idx = blockIdx.x * blockDim.x + threadIdx.x;
    int nc = idx & (NC - 1);
    int chunk = idx >> 13;
    int n = nc >> 9;

    float s = g_partial[idx];                           // idx == chunk*NC + nc
    const float* px = x   + (size_t)chunk * CHUNK * NC + nc;
    float*       po = out + (size_t)chunk * CHUNK * NC + nc;
    const float* pr = g_rcp + (size_t)chunk * CHUNK * NB + n;   // warp-uniform loads

    float last = 0.0f;
#pragma unroll 8
    for (int i = 0; i < CHUNK; i++) {
        s += px[(size_t)i * NC];
        last = s * pr[(size_t)i * NB];
        po[(size_t)i * NC] = last;
    }

    if (extras) {
        // Tuple order: [new_x | new_cached_len (as float) | new_cached_avg]
        if (chunk == NCHUNKS - 1) out[TOTAL + NB + nc] = last;  // new_x[T-1]
        if (idx < NB) out[TOTAL + idx] = (float)(cached_len[idx] + TT);
    }
}

extern "C" void kernel_launch(void* const* d_in, const int* in_sizes, int n_in,
                              void* d_out, int out_size) {
    const float* x          = (const float*)d_in[0];   // (T, N, C)
    const int*   cached_len = (const int*)d_in[1];     // (N,)
    const float* cached_avg = (const float*)d_in[2];   // (N, C)
    float* out = (float*)d_out;

    int extras = (out_size >= TOTAL + NB + NC) ? 1 : 0;

    k0_rcp   <<<(TT * NB + 255) / 256, 256>>>(cached_len);
    k1_partial<<<(NCHUNKS * NC) / 256, 256>>>(x);
    k1b_scan <<<(NC + 255) / 256, 256>>>(cached_len, cached_avg);
    k2_scan  <<<(NCHUNKS * NC) / 256, 256>>>(x, cached_len, out, extras);
}